// round 12
// baseline (speedup 1.0000x reference)
#include <cuda_runtime.h>
#include <cstdint>

#define T_LEN 16384
#define NXD 128
#define NHD 512
#define STEPS (T_LEN - NXD)   /* 16256 */
#define NGC (NHD * 4)         /* 2048 */

#define NCTA 64
#define NTHR 256     /* 8 warps, 8 outputs per CTA */

// h history: per (t,j) one u64 = (tag = t+1) << 32 | float bits of h
__device__ unsigned long long g_h64[(size_t)STEPS * NHD];   // 66 MB
// gate pre-activations, interleaved (f,i,o,c) per (t,j)
__device__ float4 g_gate4[(size_t)STEPS * NHD];             // 133 MB

__device__ __forceinline__ unsigned long long ld_rlx(const unsigned long long* p) {
    unsigned long long v;
    asm volatile("ld.relaxed.gpu.global.u64 %0, [%1];" : "=l"(v) : "l"(p) : "memory");
    return v;
}
__device__ __forceinline__ void st_rlx(unsigned long long* p, unsigned long long v) {
    asm volatile("st.relaxed.gpu.global.u64 [%0], %1;" :: "l"(p), "l"(v) : "memory");
}
__device__ __forceinline__ float tanh_hw(float x) {
    float y;
    asm("tanh.approx.f32 %0, %1;" : "=f"(y) : "f"(x));
    return y;
}
__device__ __forceinline__ float sigm(float x) {
    return fmaf(tanh_hw(0.5f * x), 0.5f, 0.5f);
}
__device__ __forceinline__ unsigned long long pack2(float lo, float hi) {
    unsigned long long r;
    asm("mov.b64 %0, {%1, %2};" : "=l"(r) : "f"(lo), "f"(hi));
    return r;
}
__device__ __forceinline__ void fma2(unsigned long long& d,
                                     unsigned long long a, unsigned long long b) {
    asm("fma.rn.f32x2 %0, %1, %2, %0;" : "+l"(d) : "l"(a), "l"(b));
}
__device__ __forceinline__ float hsum2(unsigned long long v) {
    float lo, hi;
    asm("mov.b64 {%0, %1}, %2;" : "=f"(lo), "=f"(hi) : "l"(v));
    return lo + hi;
}

// ---------------------------------------------------------------------------
// Clear tags (END of each call; device globals are zero-init for call 1)
// ---------------------------------------------------------------------------
__global__ void zero_kernel() {
    int idx = blockIdx.x * blockDim.x + threadIdx.x;
    int stride = gridDim.x * blockDim.x;
    for (int i = idx; i < STEPS * NHD; i += stride) g_h64[i] = 0ull;
}

// ---------------------------------------------------------------------------
// Gate pre-activation GEMM: gate[t][c] = b + sum_k W[c][k] * x[t+k]
// ---------------------------------------------------------------------------
__global__ void precompute_kernel(const float* __restrict__ x,
                                  const float* __restrict__ Wf, const float* __restrict__ bf,
                                  const float* __restrict__ Wi, const float* __restrict__ bi,
                                  const float* __restrict__ Wo, const float* __restrict__ bo,
                                  const float* __restrict__ Wc, const float* __restrict__ bc) {
    __shared__ float xs[192];
    __shared__ float Ws[128][65];
    const int tBase = blockIdx.x * 64;
    const int cBase = blockIdx.y * 64;
    const int tid = threadIdx.x;

    for (int i = tid; i < 191; i += 256) xs[i] = x[tBase + i];
    for (int idx = tid; idx < 8192; idx += 256) {
        int r = idx >> 7, k = idx & 127;
        int c = cBase + r;
        int j = c >> 2, g = c & 3;
        const float* W = (g == 0) ? Wf : (g == 1) ? Wi : (g == 2) ? Wo : Wc;
        Ws[k][r] = W[j * NXD + k];
    }
    __syncthreads();

    const int tx = tid & 15, ty = tid >> 4;
    const int t0 = ty * 4, r0 = tx * 4;
    float acc[4][4] = {};
#pragma unroll 4
    for (int k = 0; k < 128; k++) {
        float a0 = xs[t0 + 0 + k], a1 = xs[t0 + 1 + k];
        float a2 = xs[t0 + 2 + k], a3 = xs[t0 + 3 + k];
        float b0 = Ws[k][r0 + 0], b1 = Ws[k][r0 + 1];
        float b2 = Ws[k][r0 + 2], b3 = Ws[k][r0 + 3];
        acc[0][0] += a0 * b0; acc[0][1] += a0 * b1; acc[0][2] += a0 * b2; acc[0][3] += a0 * b3;
        acc[1][0] += a1 * b0; acc[1][1] += a1 * b1; acc[1][2] += a1 * b2; acc[1][3] += a1 * b3;
        acc[2][0] += a2 * b0; acc[2][1] += a2 * b1; acc[2][2] += a2 * b2; acc[2][3] += a2 * b3;
        acc[3][0] += a3 * b0; acc[3][1] += a3 * b1; acc[3][2] += a3 * b2; acc[3][3] += a3 * b3;
    }
    float* out = reinterpret_cast<float*>(g_gate4);
#pragma unroll
    for (int ti = 0; ti < 4; ti++) {
#pragma unroll
        for (int cj = 0; cj < 4; cj++) {
            int t = tBase + t0 + ti;
            int c = cBase + r0 + cj;
            int j = c >> 2, g = c & 3;
            float bias = (g == 0) ? bf[j] : (g == 1) ? bi[j] : (g == 2) ? bo[j] : bc[j];
            out[(size_t)t * NGC + c] = acc[ti][cj] + bias;
        }
    }
}

// ---------------------------------------------------------------------------
// Persistent self-synchronizing recurrence — R2 exchange format, 64 CTAs x
// 256 threads (8 warps, 8 outputs per CTA). Each thread polls 2 strided
// tagged-u64 slots (tid, tid+256) with immediate retry; one barrier; per-warp
// 512-dot with packed FFMA2; lane-0 epilogue. Halves total poll traffic and
// grid footprint vs R2, leaving the proven exchange mechanics untouched.
// ---------------------------------------------------------------------------
__global__ void __launch_bounds__(NTHR, 1)
lstm_rec_kernel(const float* __restrict__ Uf, const float* __restrict__ Ui,
                const float* __restrict__ Uo, const float* __restrict__ Uc) {
    __shared__ float hs[2][NHD];
    const int tid = threadIdx.x;
    const int w = tid >> 5, l = tid & 31;
    const int j = blockIdx.x * 8 + w;

    // U rows packed as f32 pairs: u2[g][m*2+p] covers h[m*128 + l*4 + 2p .. +1]
    unsigned long long u2[4][8];
    {
        const float* Us[4] = {Uf, Ui, Uo, Uc};
#pragma unroll
        for (int g = 0; g < 4; g++) {
#pragma unroll
            for (int m = 0; m < 4; m++) {
                float4 q = *reinterpret_cast<const float4*>(Us[g] + j * NHD + m * 128 + l * 4);
                u2[g][m * 2 + 0] = pack2(q.x, q.y);
                u2[g][m * 2 + 1] = pack2(q.z, q.w);
            }
        }
    }

    float cst = 0.f;
    float4 gx = make_float4(0.f, 0.f, 0.f, 0.f);
    if (l == 0) gx = g_gate4[j];   // gate inputs for t = 0

    for (int t = 0; t < STEPS; t++) {
        float* hb = hs[t & 1];
        if (t == 0) {
            hb[tid] = 0.f;
            hb[tid + 256] = 0.f;
        } else {
            const unsigned long long* src = g_h64 + (size_t)(t - 1) * NHD;
            const unsigned tt = (unsigned)t;
            // two strided polls issued back-to-back, immediate retry (R2 style)
            unsigned long long v0 = ld_rlx(src + tid);
            unsigned long long v1 = ld_rlx(src + tid + 256);
            bool o0 = (unsigned)(v0 >> 32) == tt;
            bool o1 = (unsigned)(v1 >> 32) == tt;
            while (!(o0 && o1)) {
                if (!o0) { v0 = ld_rlx(src + tid);       o0 = (unsigned)(v0 >> 32) == tt; }
                if (!o1) { v1 = ld_rlx(src + tid + 256); o1 = (unsigned)(v1 >> 32) == tt; }
            }
            hb[tid]       = __uint_as_float((unsigned)v0);
            hb[tid + 256] = __uint_as_float((unsigned)v1);
        }
        __syncthreads();

        // packed h slices (16B smem loads)
        const ulonglong2 hp0 = *reinterpret_cast<const ulonglong2*>(hb + 0   + l * 4);
        const ulonglong2 hp1 = *reinterpret_cast<const ulonglong2*>(hb + 128 + l * 4);
        const ulonglong2 hp2 = *reinterpret_cast<const ulonglong2*>(hb + 256 + l * 4);
        const ulonglong2 hp3 = *reinterpret_cast<const ulonglong2*>(hb + 384 + l * 4);

        float a0, a1, a2, a3;
        {
            unsigned long long c0 = 0ull, c1 = 0ull, c2 = 0ull, c3 = 0ull;
            fma2(c0, u2[0][0], hp0.x); fma2(c1, u2[1][0], hp0.x);
            fma2(c2, u2[2][0], hp0.x); fma2(c3, u2[3][0], hp0.x);
            fma2(c0, u2[0][1], hp0.y); fma2(c1, u2[1][1], hp0.y);
            fma2(c2, u2[2][1], hp0.y); fma2(c3, u2[3][1], hp0.y);
            fma2(c0, u2[0][2], hp1.x); fma2(c1, u2[1][2], hp1.x);
            fma2(c2, u2[2][2], hp1.x); fma2(c3, u2[3][2], hp1.x);
            fma2(c0, u2[0][3], hp1.y); fma2(c1, u2[1][3], hp1.y);
            fma2(c2, u2[2][3], hp1.y); fma2(c3, u2[3][3], hp1.y);
            fma2(c0, u2[0][4], hp2.x); fma2(c1, u2[1][4], hp2.x);
            fma2(c2, u2[2][4], hp2.x); fma2(c3, u2[3][4], hp2.x);
            fma2(c0, u2[0][5], hp2.y); fma2(c1, u2[1][5], hp2.y);
            fma2(c2, u2[2][5], hp2.y); fma2(c3, u2[3][5], hp2.y);
            fma2(c0, u2[0][6], hp3.x); fma2(c1, u2[1][6], hp3.x);
            fma2(c2, u2[2][6], hp3.x); fma2(c3, u2[3][6], hp3.x);
            fma2(c0, u2[0][7], hp3.y); fma2(c1, u2[1][7], hp3.y);
            fma2(c2, u2[2][7], hp3.y); fma2(c3, u2[3][7], hp3.y);
            a0 = hsum2(c0); a1 = hsum2(c1); a2 = hsum2(c2); a3 = hsum2(c3);
        }

#pragma unroll
        for (int off = 16; off; off >>= 1) {
            a0 += __shfl_down_sync(0xffffffffu, a0, off);
            a1 += __shfl_down_sync(0xffffffffu, a1, off);
            a2 += __shfl_down_sync(0xffffffffu, a2, off);
            a3 += __shfl_down_sync(0xffffffffu, a3, off);
        }

        if (l == 0) {
            float f = sigm(gx.x + a0);
            float i = sigm(gx.y + a1);
            float o = sigm(gx.z + a2);
            float g = tanh_hw(gx.w + a3);
            cst = f * cst + i * g;
            float h = o * tanh_hw(cst);
            st_rlx(g_h64 + (size_t)t * NHD + j,
                   ((unsigned long long)(unsigned)(t + 1) << 32) |
                   (unsigned long long)__float_as_uint(h));
            if (t + 1 < STEPS) gx = g_gate4[(size_t)(t + 1) * NHD + j];  // prefetch
        }
    }
}

// ---------------------------------------------------------------------------
// mu epilogue: out[t] = by + sum_j Ahy[j] * h[t][j]   (one warp per t)
// ---------------------------------------------------------------------------
__global__ void mu_kernel(const float* __restrict__ Ahy, const float* __restrict__ by,
                          float* __restrict__ out) {
    int gw = (int)((blockIdx.x * blockDim.x + threadIdx.x) >> 5);
    int l = threadIdx.x & 31;
    if (gw >= STEPS) return;
    const unsigned long long* hrow = g_h64 + (size_t)gw * NHD;
    float s = 0.f;
#pragma unroll
    for (int m = 0; m < 16; m++) {
        int idx = l + 32 * m;
        s += Ahy[idx] * __uint_as_float((unsigned)hrow[idx]);
    }
#pragma unroll
    for (int off = 16; off; off >>= 1) s += __shfl_down_sync(0xffffffffu, s, off);
    if (l == 0) out[gw] = s + by[0];
}

// ---------------------------------------------------------------------------
// Launch order [pre, lstm, mu, zero]: zero at the END preps tags for the next
// graph replay (device globals are zero-init for the first call).
// ---------------------------------------------------------------------------
extern "C" void kernel_launch(void* const* d_in, const int* in_sizes, int n_in,
                              void* d_out, int out_size) {
    const float* x   = (const float*)d_in[0];
    const float* Wf  = (const float*)d_in[1];
    const float* Uf  = (const float*)d_in[2];
    const float* bf  = (const float*)d_in[3];
    const float* Wi  = (const float*)d_in[4];
    const float* Ui  = (const float*)d_in[5];
    const float* bi  = (const float*)d_in[6];
    const float* Wo  = (const float*)d_in[7];
    const float* Uo  = (const float*)d_in[8];
    const float* bo  = (const float*)d_in[9];
    const float* Wc  = (const float*)d_in[10];
    const float* Uc  = (const float*)d_in[11];
    const float* bc  = (const float*)d_in[12];
    const float* Ahy = (const float*)d_in[13];
    const float* by  = (const float*)d_in[14];
    float* out = (float*)d_out;

    precompute_kernel<<<dim3(STEPS / 64, NGC / 64), 256>>>(x, Wf, bf, Wi, bi, Wo, bo, Wc, bc);
    lstm_rec_kernel<<<NCTA, NTHR>>>(Uf, Ui, Uo, Uc);
    mu_kernel<<<(STEPS * 32 + 127) / 128, 128>>>(Ahy, by, out);
    zero_kernel<<<2048, 256>>>();
    (void)in_sizes; (void)n_in; (void)out_size;
}